// round 12
// baseline (speedup 1.0000x reference)
#include <cuda_runtime.h>
#include <cuda_fp16.h>
#include <cstdint>

// TriPlane bilinear sampling, GB300 — round 12.
// Sampler identical to R11 (best: 98.5us, at ~13% over the L1 service floor).
// Transpose vectorized: float4 global reads (2 LDG.128/thread vs 8 LDG.32).

#define NPTS   1048576
#define RES    256
#define FEAT   64
#define PLANE_ELEMS (RES * RES * FEAT)

__device__ __half g_tp16[3 * PLANE_ELEMS];

// ---------------------------------------------------------------------------
// Transpose + f32->fp16 convert. grid (8, 256, 3), block 256.
// Reads 64ch x 32x tile with float4, writes [y][x][c] fp16 coalesced.
// ---------------------------------------------------------------------------
__global__ __launch_bounds__(256) void transpose_kernel(
    const float* __restrict__ p0,
    const float* __restrict__ p1,
    const float* __restrict__ p2)
{
    __shared__ float tile[FEAT][33];
    const int x0    = blockIdx.x * 32;
    const int y     = blockIdx.y;
    const int plane = blockIdx.z;
    const int tid   = threadIdx.x;

    const float* src = (plane == 0) ? p0 : (plane == 1) ? p1 : p2;

    // 64 channels x 32 x = 2048 floats = 512 float4; 2 per thread.
    #pragma unroll
    for (int i = 0; i < 2; i++) {
        int gidx = tid + i * 256;          // 0..511
        int c    = gidx >> 3;              // channel
        int x4   = gidx & 7;               // which float4 within the 32-x row
        float4 v = __ldg((const float4*)(src + c * (RES * RES) + y * RES + x0) + x4);
        tile[c][x4 * 4 + 0] = v.x;
        tile[c][x4 * 4 + 1] = v.y;
        tile[c][x4 * 4 + 2] = v.z;
        tile[c][x4 * 4 + 3] = v.w;
    }
    __syncthreads();

    __half* dst = g_tp16 + plane * PLANE_ELEMS;
    #pragma unroll
    for (int i = 0; i < 4; i++) {
        int idx = tid + i * 256;
        int xx = idx >> 5;
        int cp = idx & 31;
        float2 f = make_float2(tile[2 * cp][xx], tile[2 * cp + 1][xx]);
        ((half2*)(dst + ((y * RES + (x0 + xx)) * FEAT)))[cp] = __float22half2_rn(f);
    }
}

// ---------------------------------------------------------------------------
// Sampler (unchanged from R11): 16 lanes/point, LDG.64 (2 lines/instr),
// 12 loads upfront, half2 accumulation.
// ---------------------------------------------------------------------------
__device__ __forceinline__ void plane_setup(float u, float v,
                                            int& t00, half2 w[4]) {
    float ix = (u + 1.0f) * 0.5f * (float)(RES - 1);
    float iy = (v + 1.0f) * 0.5f * (float)(RES - 1);
    float fx0 = floorf(ix);
    float fy0 = floorf(iy);

    float wx1 = ix - fx0;
    float wx0 = (fx0 + 1.0f) - ix;
    float wy1 = iy - fy0;
    float wy0 = (fy0 + 1.0f) - iy;

    int x0 = (int)fx0;               // u,v in [-1,1): no clamps needed
    int y0 = (int)fy0;
    t00 = (y0 << 12) + (x0 << 4);    // uint2 offset of texel (y0,x0)

    w[0] = __float2half2_rn(wx0 * wy0);
    w[1] = __float2half2_rn(wx1 * wy0);
    w[2] = __float2half2_rn(wx0 * wy1);
    w[3] = __float2half2_rn(wx1 * wy1);
}

__device__ __forceinline__ void plane_reduce(const uint2& r00, const uint2& r01,
                                             const uint2& r10, const uint2& r11,
                                             const half2 w[4], half2 acc[2]) {
    const half2* h00 = (const half2*)&r00;
    const half2* h01 = (const half2*)&r01;
    const half2* h10 = (const half2*)&r10;
    const half2* h11 = (const half2*)&r11;
    #pragma unroll
    for (int j = 0; j < 2; j++) {
        half2 a = acc[j];
        a = __hfma2(w[0], h00[j], a);
        a = __hfma2(w[1], h01[j], a);
        a = __hfma2(w[2], h10[j], a);
        a = __hfma2(w[3], h11[j], a);
        acc[j] = a;
    }
}

__global__ __launch_bounds__(256) void sample_kernel(const float* __restrict__ x,
                                                     float* __restrict__ out) {
    const int gtid = blockIdx.x * blockDim.x + threadIdx.x;
    const int p    = gtid >> 4;       // point index (16 lanes/point)
    const int sub  = gtid & 15;       // 4-channel group

    const float px = __ldg(x + 3 * p + 0);
    const float py = __ldg(x + 3 * p + 1);
    const float pz = __ldg(x + 3 * p + 2);

    int tA, tB, tC;
    half2 wA[4], wB[4], wC[4];
    plane_setup(px, py, tA, wA);
    plane_setup(px, pz, tB, wB);
    plane_setup(py, pz, tC, wC);

    const uint2* qA = (const uint2*)(g_tp16 + 0 * PLANE_ELEMS) + sub + tA;
    const uint2* qB = (const uint2*)(g_tp16 + 1 * PLANE_ELEMS) + sub + tB;
    const uint2* qC = (const uint2*)(g_tp16 + 2 * PLANE_ELEMS) + sub + tC;

    // All 12 loads issued before any consumption (MLP = 12).
    uint2 ra0 = __ldg(qA);
    uint2 ra1 = __ldg(qA + 16);
    uint2 ra2 = __ldg(qA + 4096);
    uint2 ra3 = __ldg(qA + 4112);
    uint2 rb0 = __ldg(qB);
    uint2 rb1 = __ldg(qB + 16);
    uint2 rb2 = __ldg(qB + 4096);
    uint2 rb3 = __ldg(qB + 4112);
    uint2 rc0 = __ldg(qC);
    uint2 rc1 = __ldg(qC + 16);
    uint2 rc2 = __ldg(qC + 4096);
    uint2 rc3 = __ldg(qC + 4112);

    half2 acc[2];
    acc[0] = __float2half2_rn(0.0f);
    acc[1] = __float2half2_rn(0.0f);

    plane_reduce(ra0, ra1, ra2, ra3, wA, acc);
    plane_reduce(rb0, rb1, rb2, rb3, wB, acc);
    plane_reduce(rc0, rc1, rc2, rc3, wC, acc);

    const float inv3 = 1.0f / 3.0f;
    float2 f0 = __half22float2(acc[0]);
    float2 f1 = __half22float2(acc[1]);
    float4 o = make_float4(f0.x * inv3, f0.y * inv3, f1.x * inv3, f1.y * inv3);
    ((float4*)(out + p * FEAT))[sub] = o;
}

// ---------------------------------------------------------------------------
extern "C" void kernel_launch(void* const* d_in, const int* in_sizes, int n_in,
                              void* d_out, int out_size) {
    const float* x        = (const float*)d_in[0];
    const float* plane_xy = (const float*)d_in[1];
    const float* plane_xz = (const float*)d_in[2];
    const float* plane_yz = (const float*)d_in[3];
    float* out = (float*)d_out;

    dim3 tgrid(RES / 32, RES, 3);
    transpose_kernel<<<tgrid, 256>>>(plane_xy, plane_xz, plane_yz);

    const int threads = 256;
    const int blocks  = (NPTS * 16) / threads;   // 16 lanes per point
    sample_kernel<<<blocks, threads>>>(x, out);
}